// round 1
// baseline (speedup 1.0000x reference)
#include <cuda_runtime.h>
#include <math.h>

#define B_   16
#define CLEN 4096
#define QLEN 512
#define H    256

// Scratch (device globals: allocation-free per harness rules)
__device__ float g_S[(size_t)B_ * CLEN * QLEN];   // 128 MB: S, then softmaxed A (in place)
__device__ float g_u[B_ * CLEN];                  // c.w_c + b_c
__device__ float g_v[B_ * QLEN];                  // q.w_q + b_q + b_cq
__device__ float g_m[B_ * CLEN];                  // rowmax of s (full, incl. u)
__device__ float g_q2c[B_ * H];                   // q2c attention vector per batch

// ---------------------------------------------------------------------------
// Kernel 1: u[b,i] = c_i.w_c + b_c ; v[b,j] = q_j.w_q + b_q + b_cq
// one warp per row
// ---------------------------------------------------------------------------
__global__ __launch_bounds__(256) void uv_kernel(
    const float* __restrict__ c, const float* __restrict__ q,
    const float* __restrict__ w_c, const float* __restrict__ b_c,
    const float* __restrict__ w_q, const float* __restrict__ b_q,
    const float* __restrict__ b_cq)
{
    int warp = (blockIdx.x * blockDim.x + threadIdx.x) >> 5;
    int lane = threadIdx.x & 31;
    if (warp < B_ * CLEN) {
        const float* row = c + (size_t)warp * H;
        float s = 0.f;
        #pragma unroll
        for (int t = 0; t < H / 32; t++) s = fmaf(row[lane + t * 32], w_c[lane + t * 32], s);
        #pragma unroll
        for (int o = 16; o; o >>= 1) s += __shfl_xor_sync(0xffffffffu, s, o);
        if (lane == 0) g_u[warp] = s + b_c[0];
    } else {
        int r = warp - B_ * CLEN;
        if (r < B_ * QLEN) {
            const float* row = q + (size_t)r * H;
            float s = 0.f;
            #pragma unroll
            for (int t = 0; t < H / 32; t++) s = fmaf(row[lane + t * 32], w_q[lane + t * 32], s);
            #pragma unroll
            for (int o = 16; o; o >>= 1) s += __shfl_xor_sync(0xffffffffu, s, o);
            if (lane == 0) g_v[r] = s + b_q[0] + b_cq[0];
        }
    }
}

// ---------------------------------------------------------------------------
// Kernel 2: S[b,i,j] = sum_d (c[b,i,d]*w_cq[d]) * q[b,j,d]  + v[b,j]
// NT SGEMM: M=CLEN, N=QLEN, K=H.  BM=BN=128, BK=16, 256 threads, 8x8/thread.
// ---------------------------------------------------------------------------
__global__ __launch_bounds__(256) void gemm1_kernel(
    const float* __restrict__ c, const float* __restrict__ q,
    const float* __restrict__ w_cq)
{
    __shared__ float As[16][128];   // [k][m]
    __shared__ float Bs[16][128];   // [k][n]
    const int b  = blockIdx.z;
    const int m0 = blockIdx.y * 128;
    const int n0 = blockIdx.x * 128;
    const int tid = threadIdx.x;
    const int tx = tid & 15;        // n-frag
    const int ty = tid >> 4;        // m-frag
    const int lr = tid >> 1;        // 0..127  load row
    const int lk = (tid & 1) * 8;   // 0/8     load k-offset

    const float* Ab = c + ((size_t)b * CLEN + m0 + lr) * H + lk;
    const float* Bb = q + ((size_t)b * QLEN + n0 + lr) * H + lk;

    float acc[8][8];
    #pragma unroll
    for (int i = 0; i < 8; i++)
        #pragma unroll
        for (int j = 0; j < 8; j++) acc[i][j] = 0.f;

    for (int k0 = 0; k0 < H; k0 += 16) {
        float4 a0 = *(const float4*)(Ab + k0);
        float4 a1 = *(const float4*)(Ab + k0 + 4);
        float4 w0 = *(const float4*)(w_cq + k0 + lk);
        float4 w1 = *(const float4*)(w_cq + k0 + lk + 4);
        float4 q0 = *(const float4*)(Bb + k0);
        float4 q1 = *(const float4*)(Bb + k0 + 4);
        As[lk + 0][lr] = a0.x * w0.x; As[lk + 1][lr] = a0.y * w0.y;
        As[lk + 2][lr] = a0.z * w0.z; As[lk + 3][lr] = a0.w * w0.w;
        As[lk + 4][lr] = a1.x * w1.x; As[lk + 5][lr] = a1.y * w1.y;
        As[lk + 6][lr] = a1.z * w1.z; As[lk + 7][lr] = a1.w * w1.w;
        Bs[lk + 0][lr] = q0.x; Bs[lk + 1][lr] = q0.y;
        Bs[lk + 2][lr] = q0.z; Bs[lk + 3][lr] = q0.w;
        Bs[lk + 4][lr] = q1.x; Bs[lk + 5][lr] = q1.y;
        Bs[lk + 6][lr] = q1.z; Bs[lk + 7][lr] = q1.w;
        __syncthreads();
        #pragma unroll
        for (int kk = 0; kk < 16; kk++) {
            float ar[8], br[8];
            *(float4*)&ar[0] = *(const float4*)&As[kk][ty * 8];
            *(float4*)&ar[4] = *(const float4*)&As[kk][ty * 8 + 4];
            *(float4*)&br[0] = *(const float4*)&Bs[kk][tx * 8];
            *(float4*)&br[4] = *(const float4*)&Bs[kk][tx * 8 + 4];
            #pragma unroll
            for (int i = 0; i < 8; i++)
                #pragma unroll
                for (int j = 0; j < 8; j++)
                    acc[i][j] = fmaf(ar[i], br[j], acc[i][j]);
        }
        __syncthreads();
    }

    float* Srow = g_S + ((size_t)b * CLEN + m0 + ty * 8) * QLEN + n0 + tx * 8;
    const float* vb = g_v + b * QLEN + n0 + tx * 8;
    float4 v0 = *(const float4*)(vb);
    float4 v1 = *(const float4*)(vb + 4);
    #pragma unroll
    for (int i = 0; i < 8; i++) {
        float4 o0 = make_float4(acc[i][0] + v0.x, acc[i][1] + v0.y,
                                acc[i][2] + v0.z, acc[i][3] + v0.w);
        float4 o1 = make_float4(acc[i][4] + v1.x, acc[i][5] + v1.y,
                                acc[i][6] + v1.z, acc[i][7] + v1.w);
        *(float4*)(Srow + (size_t)i * QLEN)     = o0;
        *(float4*)(Srow + (size_t)i * QLEN + 4) = o1;
    }
}

// ---------------------------------------------------------------------------
// Kernel 3: per-row softmax over j (512), in place; m = rowmax + u
// one warp per row, 16 elems/lane
// ---------------------------------------------------------------------------
__global__ __launch_bounds__(256) void softmax_kernel()
{
    int warp = (blockIdx.x * blockDim.x + threadIdx.x) >> 5;
    if (warp >= B_ * CLEN) return;
    int lane = threadIdx.x & 31;
    float* row = g_S + (size_t)warp * QLEN;

    float v[16];
    float mx = -3.402823466e38f;
    #pragma unroll
    for (int t = 0; t < 16; t++) { v[t] = row[lane + t * 32]; mx = fmaxf(mx, v[t]); }
    #pragma unroll
    for (int o = 16; o; o >>= 1) mx = fmaxf(mx, __shfl_xor_sync(0xffffffffu, mx, o));
    float s = 0.f;
    #pragma unroll
    for (int t = 0; t < 16; t++) { v[t] = __expf(v[t] - mx); s += v[t]; }
    #pragma unroll
    for (int o = 16; o; o >>= 1) s += __shfl_xor_sync(0xffffffffu, s, o);
    float inv = 1.f / s;
    #pragma unroll
    for (int t = 0; t < 16; t++) row[lane + t * 32] = v[t] * inv;
    if (lane == 0) g_m[warp] = mx + g_u[warp];
}

// ---------------------------------------------------------------------------
// Kernel 4: per batch: b_att = softmax_i(m), q2c[d] = sum_i b_att_i * c[b,i,d]
// one 1024-thread CTA per batch (4 i-partitions x 256 d)
// ---------------------------------------------------------------------------
__global__ __launch_bounds__(1024) void q2c_kernel(const float* __restrict__ c)
{
    __shared__ float w[CLEN];      // 16 KB exp weights
    __shared__ float red[32];
    __shared__ float part[4 * H];  // 4 KB partials
    const int b   = blockIdx.x;
    const int tid = threadIdx.x;
    const float* m = g_m + b * CLEN;

    float mx = -3.402823466e38f;
    for (int i = tid; i < CLEN; i += 1024) mx = fmaxf(mx, m[i]);
    #pragma unroll
    for (int o = 16; o; o >>= 1) mx = fmaxf(mx, __shfl_xor_sync(0xffffffffu, mx, o));
    if ((tid & 31) == 0) red[tid >> 5] = mx;
    __syncthreads();
    float bm = red[0];
    #pragma unroll
    for (int i = 1; i < 32; i++) bm = fmaxf(bm, red[i]);
    __syncthreads();

    float s = 0.f;
    for (int i = tid; i < CLEN; i += 1024) {
        float e = __expf(m[i] - bm);
        w[i] = e;
        s += e;
    }
    #pragma unroll
    for (int o = 16; o; o >>= 1) s += __shfl_xor_sync(0xffffffffu, s, o);
    if ((tid & 31) == 0) red[tid >> 5] = s;
    __syncthreads();
    float Z = 0.f;
    #pragma unroll
    for (int i = 0; i < 32; i++) Z += red[i];

    const int d = tid & 255;
    const int p = tid >> 8;     // 0..3
    const float* cb = c + (size_t)b * CLEN * H + d;
    float acc = 0.f;
    const int i0 = p * (CLEN / 4), i1 = i0 + (CLEN / 4);
    #pragma unroll 8
    for (int i = i0; i < i1; i++) acc = fmaf(w[i], cb[(size_t)i * H], acc);
    part[p * H + d] = acc;
    __syncthreads();
    if (p == 0) {
        float t = part[d] + part[H + d] + part[2 * H + d] + part[3 * H + d];
        g_q2c[b * H + d] = t / Z;
    }
}

// ---------------------------------------------------------------------------
// Kernel 5: c2q = A @ q  (NN SGEMM M=CLEN, N=H, K=QLEN), fused output epilogue:
// out[:,:,0:H]=c, [H:2H]=c2q, [2H:3H]=c*c2q, [3H:4H]=c*q2c
// ---------------------------------------------------------------------------
__global__ __launch_bounds__(256) void gemm2_kernel(
    const float* __restrict__ c, const float* __restrict__ q,
    float* __restrict__ out)
{
    __shared__ float As[16][128];   // [k][m]  A = softmaxed S
    __shared__ float Bs[16][128];   // [k][n]  B = q
    const int b  = blockIdx.z;
    const int m0 = blockIdx.y * 128;
    const int n0 = blockIdx.x * 128;
    const int tid = threadIdx.x;
    const int tx = tid & 15;
    const int ty = tid >> 4;
    const int lr = tid >> 1;
    const int lk = (tid & 1) * 8;
    const int bj = tid >> 4;        // 0..15 (k row of B tile)
    const int bd = (tid & 15) * 8;  // n offset

    const float* Ab = g_S + ((size_t)b * CLEN + m0 + lr) * QLEN + lk;
    const float* Bb = q + (size_t)b * QLEN * H + n0;

    float acc[8][8];
    #pragma unroll
    for (int i = 0; i < 8; i++)
        #pragma unroll
        for (int j = 0; j < 8; j++) acc[i][j] = 0.f;

    for (int k0 = 0; k0 < QLEN; k0 += 16) {
        float4 a0 = *(const float4*)(Ab + k0);
        float4 a1 = *(const float4*)(Ab + k0 + 4);
        As[lk + 0][lr] = a0.x; As[lk + 1][lr] = a0.y;
        As[lk + 2][lr] = a0.z; As[lk + 3][lr] = a0.w;
        As[lk + 4][lr] = a1.x; As[lk + 5][lr] = a1.y;
        As[lk + 6][lr] = a1.z; As[lk + 7][lr] = a1.w;
        float4 q0 = *(const float4*)(Bb + (size_t)(k0 + bj) * H + bd);
        float4 q1 = *(const float4*)(Bb + (size_t)(k0 + bj) * H + bd + 4);
        *(float4*)&Bs[bj][bd]     = q0;
        *(float4*)&Bs[bj][bd + 4] = q1;
        __syncthreads();
        #pragma unroll
        for (int kk = 0; kk < 16; kk++) {
            float ar[8], br[8];
            *(float4*)&ar[0] = *(const float4*)&As[kk][ty * 8];
            *(float4*)&ar[4] = *(const float4*)&As[kk][ty * 8 + 4];
            *(float4*)&br[0] = *(const float4*)&Bs[kk][tx * 8];
            *(float4*)&br[4] = *(const float4*)&Bs[kk][tx * 8 + 4];
            #pragma unroll
            for (int i = 0; i < 8; i++)
                #pragma unroll
                for (int j = 0; j < 8; j++)
                    acc[i][j] = fmaf(ar[i], br[j], acc[i][j]);
        }
        __syncthreads();
    }

    const float* q2cb = g_q2c + b * H + n0 + tx * 8;
    float4 g0 = *(const float4*)(q2cb);
    float4 g1 = *(const float4*)(q2cb + 4);
    #pragma unroll
    for (int i = 0; i < 8; i++) {
        int row = m0 + ty * 8 + i;
        const float* crow = c + ((size_t)b * CLEN + row) * H + n0 + tx * 8;
        float4 c0 = *(const float4*)crow;
        float4 c1 = *(const float4*)(crow + 4);
        float* orow = out + ((size_t)b * CLEN + row) * (4 * H) + n0 + tx * 8;
        float4 o0 = make_float4(acc[i][0], acc[i][1], acc[i][2], acc[i][3]);
        float4 o1 = make_float4(acc[i][4], acc[i][5], acc[i][6], acc[i][7]);
        *(float4*)(orow)              = c0;
        *(float4*)(orow + 4)          = c1;
        *(float4*)(orow + H)          = o0;
        *(float4*)(orow + H + 4)      = o1;
        *(float4*)(orow + 2 * H)      = make_float4(c0.x * o0.x, c0.y * o0.y, c0.z * o0.z, c0.w * o0.w);
        *(float4*)(orow + 2 * H + 4)  = make_float4(c1.x * o1.x, c1.y * o1.y, c1.z * o1.z, c1.w * o1.w);
        *(float4*)(orow + 3 * H)      = make_float4(c0.x * g0.x, c0.y * g0.y, c0.z * g0.z, c0.w * g0.w);
        *(float4*)(orow + 3 * H + 4)  = make_float4(c1.x * g1.x, c1.y * g1.y, c1.z * g1.z, c1.w * g1.w);
    }
}

// ---------------------------------------------------------------------------
extern "C" void kernel_launch(void* const* d_in, const int* in_sizes, int n_in,
                              void* d_out, int out_size)
{
    const float* c    = (const float*)d_in[0];
    const float* q    = (const float*)d_in[1];
    const float* w_c  = (const float*)d_in[2];
    const float* b_c  = (const float*)d_in[3];
    const float* w_q  = (const float*)d_in[4];
    const float* b_q  = (const float*)d_in[5];
    const float* w_cq = (const float*)d_in[6];
    const float* b_cq = (const float*)d_in[7];
    float* out = (float*)d_out;

    // 1. row dots u, v
    {
        int warps = B_ * CLEN + B_ * QLEN;
        int blocks = (warps * 32 + 255) / 256;
        uv_kernel<<<blocks, 256>>>(c, q, w_c, b_c, w_q, b_q, b_cq);
    }
    // 2. S = (c.w_cq) q^T + v
    {
        dim3 grid(QLEN / 128, CLEN / 128, B_);
        gemm1_kernel<<<grid, 256>>>(c, q, w_cq);
    }
    // 3. row softmax + row max
    {
        int warps = B_ * CLEN;
        int blocks = (warps * 32 + 255) / 256;
        softmax_kernel<<<blocks, 256>>>();
    }
    // 4. q2c attention
    q2c_kernel<<<B_, 1024>>>(c);
    // 5. c2q + fused output
    {
        dim3 grid(H / 128, CLEN / 128, B_);
        gemm2_kernel<<<grid, 256>>>(c, q, out);
    }
}

// round 2
// speedup vs baseline: 2.4724x; 2.4724x over previous
#include <cuda_runtime.h>
#include <math.h>
#include <stdint.h>

#define B_   16
#define CLEN 4096
#define QLEN 512
#define H    256

// ---- scratch (device globals; allocation-free) ----
__device__ __align__(128) float g_S [(size_t)B_*CLEN*QLEN];  // S, then softmaxed A (tf32-rounded)
__device__ __align__(128) float g_cr[(size_t)B_*CLEN*H];     // c rounded to tf32
__device__ __align__(128) float g_qr[(size_t)B_*QLEN*H];     // q rounded to tf32
__device__ __align__(128) float g_qs[(size_t)B_*QLEN*H];     // (q*w_cq) rounded to tf32
__device__ float g_u[B_*CLEN];
__device__ float g_v[B_*QLEN];
__device__ float g_m[B_*CLEN];
__device__ float g_bm[B_];
__device__ float g_Z[B_];
__device__ float g_part[B_*32*H];
__device__ float g_q2c[B_*H];

__device__ __forceinline__ float rtf(float x){
    uint32_t u; asm("cvt.rna.tf32.f32 %0, %1;" : "=r"(u) : "f"(x));
    return __uint_as_float(u);
}

#define CPA16(s,g)  asm volatile("cp.async.cg.shared.global [%0], [%1], 16;\n" :: "r"(s), "l"(g))
#define CPCOMMIT()  asm volatile("cp.async.commit_group;\n")
#define CPWAIT(n)   asm volatile("cp.async.wait_group %0;\n" :: "n"(n))

__device__ __forceinline__ void mma_tf32(float* d, const uint32_t* a, const uint32_t* b){
    asm volatile("mma.sync.aligned.m16n8k8.row.col.f32.tf32.tf32.f32 "
        "{%0,%1,%2,%3}, {%4,%5,%6,%7}, {%8,%9}, {%0,%1,%2,%3};"
        : "+f"(d[0]),"+f"(d[1]),"+f"(d[2]),"+f"(d[3])
        : "r"(a[0]),"r"(a[1]),"r"(a[2]),"r"(a[3]), "r"(b[0]),"r"(b[1]));
}

// ---------------------------------------------------------------------------
// prep: round c->g_cr, q->g_qr, q*w_cq->g_qs  (all tf32-RNA)
// ---------------------------------------------------------------------------
__global__ __launch_bounds__(256) void prep_kernel(
    const float4* __restrict__ c, const float4* __restrict__ q,
    const float4* __restrict__ w)
{
    size_t i = (size_t)blockIdx.x * 256 + threadIdx.x;
    const size_t NC4 = (size_t)B_*CLEN*(H/4);
    const size_t NQ4 = (size_t)B_*QLEN*(H/4);
    if (i < NC4) {
        float4 x = c[i];
        ((float4*)g_cr)[i] = make_float4(rtf(x.x), rtf(x.y), rtf(x.z), rtf(x.w));
    } else if (i < NC4 + NQ4) {
        size_t j = i - NC4;
        float4 x = q[j];
        float4 wv = w[j & (H/4 - 1)];
        ((float4*)g_qr)[j] = make_float4(rtf(x.x), rtf(x.y), rtf(x.z), rtf(x.w));
        ((float4*)g_qs)[j] = make_float4(rtf(x.x*wv.x), rtf(x.y*wv.y),
                                         rtf(x.z*wv.z), rtf(x.w*wv.w));
    }
}

// ---------------------------------------------------------------------------
// uv: u[b,i] = c_i.w_c + b_c ; v[b,j] = q_j.w_q + b_q + b_cq   (one warp/row)
// ---------------------------------------------------------------------------
__global__ __launch_bounds__(256) void uv_kernel(
    const float* __restrict__ c, const float* __restrict__ q,
    const float* __restrict__ w_c, const float* __restrict__ b_c,
    const float* __restrict__ w_q, const float* __restrict__ b_q,
    const float* __restrict__ b_cq)
{
    int warp = (blockIdx.x * blockDim.x + threadIdx.x) >> 5;
    int lane = threadIdx.x & 31;
    if (warp < B_ * CLEN) {
        const float* row = c + (size_t)warp * H;
        float s = 0.f;
        #pragma unroll
        for (int t = 0; t < H/32; t++) s = fmaf(row[lane + t*32], w_c[lane + t*32], s);
        #pragma unroll
        for (int o = 16; o; o >>= 1) s += __shfl_xor_sync(0xffffffffu, s, o);
        if (lane == 0) g_u[warp] = s + b_c[0];
    } else {
        int r = warp - B_ * CLEN;
        if (r < B_ * QLEN) {
            const float* row = q + (size_t)r * H;
            float s = 0.f;
            #pragma unroll
            for (int t = 0; t < H/32; t++) s = fmaf(row[lane + t*32], w_q[lane + t*32], s);
            #pragma unroll
            for (int o = 16; o; o >>= 1) s += __shfl_xor_sync(0xffffffffu, s, o);
            if (lane == 0) g_v[r] = s + b_q[0] + b_cq[0];
        }
    }
}

// ---------------------------------------------------------------------------
// GEMM1 (tf32 mma): S[b,i,j] = sum_d cr[b,i,d]*qs[b,j,d] + v[b,j]
// CTA tile 128x128, BK=16, double-buffered cp.async, 8 warps (2x4), warp 64x32
// ---------------------------------------------------------------------------
__global__ __launch_bounds__(256,2) void gemm1_tc()
{
    __shared__ float As[2][128][20];   // [stage][m][k]
    __shared__ float Bs[2][128][20];   // [stage][n][k]
    const int b  = blockIdx.z, m0 = blockIdx.y*128, n0 = blockIdx.x*128;
    const int tid = threadIdx.x;
    const int lane = tid & 31, wid = tid >> 5;
    const int wm = wid >> 2, wn = wid & 3;
    const int gid = lane >> 2, tig = lane & 3;
    const int cm = tid >> 2, ck = (tid & 3) * 4;

    const float* Ag = g_cr + ((size_t)b*CLEN + m0 + cm)*H + ck;
    const float* Bg = g_qs + ((size_t)b*QLEN + n0 + cm)*H + ck;
    const uint32_t sA = (uint32_t)__cvta_generic_to_shared(&As[0][cm][ck]);
    const uint32_t sB = (uint32_t)__cvta_generic_to_shared(&Bs[0][cm][ck]);

    float acc[4][4][4];
    #pragma unroll
    for (int i = 0; i < 4; i++)
        #pragma unroll
        for (int j = 0; j < 4; j++)
            #pragma unroll
            for (int r = 0; r < 4; r++) acc[i][j][r] = 0.f;

    // stage 0 load
    CPA16(sA, Ag); CPA16(sA + 5120u, Ag + (size_t)64*H);
    CPA16(sB, Bg); CPA16(sB + 5120u, Bg + (size_t)64*H);
    CPCOMMIT();

    for (int i = 0; i < H/16; i++) {
        const int st = i & 1;
        if (i + 1 < H/16) {
            const int kc = (i+1)*16;
            const uint32_t oa = sA + (st^1)*10240u, ob = sB + (st^1)*10240u;
            CPA16(oa, Ag + kc); CPA16(oa + 5120u, Ag + (size_t)64*H + kc);
            CPA16(ob, Bg + kc); CPA16(ob + 5120u, Bg + (size_t)64*H + kc);
            CPCOMMIT();
            CPWAIT(1);
        } else {
            CPWAIT(0);
        }
        __syncthreads();
        #pragma unroll
        for (int kk = 0; kk < 16; kk += 8) {
            uint32_t a[4][4], bf[4][2];
            #pragma unroll
            for (int mt = 0; mt < 4; mt++) {
                int m = wm*64 + mt*16 + gid;
                a[mt][0] = __float_as_uint(As[st][m    ][kk+tig  ]);
                a[mt][1] = __float_as_uint(As[st][m + 8][kk+tig  ]);
                a[mt][2] = __float_as_uint(As[st][m    ][kk+tig+4]);
                a[mt][3] = __float_as_uint(As[st][m + 8][kk+tig+4]);
            }
            #pragma unroll
            for (int nt = 0; nt < 4; nt++) {
                int n = wn*32 + nt*8 + gid;
                bf[nt][0] = __float_as_uint(Bs[st][n][kk+tig  ]);
                bf[nt][1] = __float_as_uint(Bs[st][n][kk+tig+4]);
            }
            #pragma unroll
            for (int mt = 0; mt < 4; mt++)
                #pragma unroll
                for (int nt = 0; nt < 4; nt++)
                    mma_tf32(acc[mt][nt], a[mt], bf[nt]);
        }
        __syncthreads();
    }

    // epilogue: +v, write S
    const float* vb = g_v + b*QLEN + n0 + wn*32;
    float2 vv[4];
    #pragma unroll
    for (int nt = 0; nt < 4; nt++) vv[nt] = *(const float2*)&vb[nt*8 + 2*tig];
    #pragma unroll
    for (int mt = 0; mt < 4; mt++)
        #pragma unroll
        for (int r = 0; r < 2; r++) {
            int row = m0 + wm*64 + mt*16 + gid + 8*r;
            float* p = g_S + ((size_t)b*CLEN + row)*QLEN + n0 + wn*32;
            #pragma unroll
            for (int nt = 0; nt < 4; nt++) {
                float2 o = make_float2(acc[mt][nt][2*r] + vv[nt].x,
                                       acc[mt][nt][2*r+1] + vv[nt].y);
                *(float2*)&p[nt*8 + 2*tig] = o;
            }
        }
}

// ---------------------------------------------------------------------------
// softmax over j (512) in place (stores tf32-rounded probs); m = rowmax + u
// ---------------------------------------------------------------------------
__global__ __launch_bounds__(256) void softmax_kernel()
{
    int warp = (blockIdx.x * blockDim.x + threadIdx.x) >> 5;
    if (warp >= B_ * CLEN) return;
    int lane = threadIdx.x & 31;
    float* row = g_S + (size_t)warp * QLEN;

    float v[16];
    float mx = -3.402823466e38f;
    #pragma unroll
    for (int t = 0; t < 16; t++) { v[t] = row[lane + t*32]; mx = fmaxf(mx, v[t]); }
    #pragma unroll
    for (int o = 16; o; o >>= 1) mx = fmaxf(mx, __shfl_xor_sync(0xffffffffu, mx, o));
    float s = 0.f;
    #pragma unroll
    for (int t = 0; t < 16; t++) { v[t] = __expf(v[t] - mx); s += v[t]; }
    #pragma unroll
    for (int o = 16; o; o >>= 1) s += __shfl_xor_sync(0xffffffffu, s, o);
    float inv = 1.f / s;
    #pragma unroll
    for (int t = 0; t < 16; t++) row[lane + t*32] = rtf(v[t] * inv);
    if (lane == 0) g_m[warp] = mx + g_u[warp];
}

// ---------------------------------------------------------------------------
// q2c: (a) per-batch max & Z over m; (b) 512-CTA partial sums; (c) reduce
// ---------------------------------------------------------------------------
__global__ __launch_bounds__(256) void bmz_kernel()
{
    int b = blockIdx.x, tid = threadIdx.x;
    __shared__ float red[8];
    const float* m = g_m + b*CLEN;
    float mx = -3.402823466e38f;
    for (int i = tid; i < CLEN; i += 256) mx = fmaxf(mx, m[i]);
    #pragma unroll
    for (int o = 16; o; o >>= 1) mx = fmaxf(mx, __shfl_xor_sync(0xffffffffu, mx, o));
    if ((tid & 31) == 0) red[tid >> 5] = mx;
    __syncthreads();
    mx = red[0];
    #pragma unroll
    for (int i = 1; i < 8; i++) mx = fmaxf(mx, red[i]);
    __syncthreads();
    float s = 0.f;
    for (int i = tid; i < CLEN; i += 256) s += __expf(m[i] - mx);
    #pragma unroll
    for (int o = 16; o; o >>= 1) s += __shfl_xor_sync(0xffffffffu, s, o);
    if ((tid & 31) == 0) red[tid >> 5] = s;
    __syncthreads();
    if (tid == 0) {
        float Z = 0.f;
        #pragma unroll
        for (int i = 0; i < 8; i++) Z += red[i];
        g_bm[b] = mx; g_Z[b] = Z;
    }
}

__global__ __launch_bounds__(256) void q2c_part(const float* __restrict__ c)
{
    const int b = blockIdx.y, p = blockIdx.x, tid = threadIdx.x;
    __shared__ float w[128];
    if (tid < 128) w[tid] = __expf(g_m[b*CLEN + p*128 + tid] - g_bm[b]);
    __syncthreads();
    const float invZ = 1.f / g_Z[b];
    const float* cb = c + ((size_t)b*CLEN + p*128)*H + tid;
    float acc = 0.f;
    #pragma unroll 8
    for (int i = 0; i < 128; i++) acc = fmaf(w[i], cb[(size_t)i*H], acc);
    g_part[(b*32 + p)*H + tid] = acc * invZ;
}

__global__ __launch_bounds__(256) void q2c_reduce()
{
    int b = blockIdx.x, d = threadIdx.x;
    float s = 0.f;
    #pragma unroll
    for (int p = 0; p < 32; p++) s += g_part[(b*32 + p)*H + d];
    g_q2c[b*H + d] = s;
}

// ---------------------------------------------------------------------------
// GEMM2 (tf32 mma): c2q = A @ q_r, fused 4-section output epilogue
// ---------------------------------------------------------------------------
__global__ __launch_bounds__(256,2) void gemm2_tc(
    const float* __restrict__ c, float* __restrict__ out)
{
    __shared__ float As[2][128][20];   // [stage][m][k]  A = probs
    __shared__ float Bs[2][16][136];   // [stage][k][n]  B = q_r
    const int b  = blockIdx.z, m0 = blockIdx.y*128, n0 = blockIdx.x*128;
    const int tid = threadIdx.x;
    const int lane = tid & 31, wid = tid >> 5;
    const int wm = wid >> 2, wn = wid & 3;
    const int gid = lane >> 2, tig = lane & 3;
    const int cm = tid >> 2, ck = (tid & 3) * 4;    // A copy
    const int bk = tid >> 4, bn = (tid & 15) * 4;   // B copy

    const float* Ag = g_S  + ((size_t)b*CLEN + m0 + cm)*QLEN + ck;
    const float* Bg = g_qr + ((size_t)b*QLEN + bk)*H + n0 + bn;
    const uint32_t sA = (uint32_t)__cvta_generic_to_shared(&As[0][cm][ck]);
    const uint32_t sB = (uint32_t)__cvta_generic_to_shared(&Bs[0][bk][bn]);

    float acc[4][4][4];
    #pragma unroll
    for (int i = 0; i < 4; i++)
        #pragma unroll
        for (int j = 0; j < 4; j++)
            #pragma unroll
            for (int r = 0; r < 4; r++) acc[i][j][r] = 0.f;

    CPA16(sA, Ag); CPA16(sA + 5120u, Ag + (size_t)64*QLEN);
    CPA16(sB, Bg); CPA16(sB + 256u, Bg + 64);
    CPCOMMIT();

    for (int i = 0; i < QLEN/16; i++) {
        const int st = i & 1;
        if (i + 1 < QLEN/16) {
            const int kc = (i+1)*16;
            const uint32_t oa = sA + (st^1)*10240u, ob = sB + (st^1)*8704u;
            CPA16(oa, Ag + kc); CPA16(oa + 5120u, Ag + (size_t)64*QLEN + kc);
            CPA16(ob, Bg + (size_t)kc*H); CPA16(ob + 256u, Bg + (size_t)kc*H + 64);
            CPCOMMIT();
            CPWAIT(1);
        } else {
            CPWAIT(0);
        }
        __syncthreads();
        #pragma unroll
        for (int kk = 0; kk < 16; kk += 8) {
            uint32_t a[4][4], bf[4][2];
            #pragma unroll
            for (int mt = 0; mt < 4; mt++) {
                int m = wm*64 + mt*16 + gid;
                a[mt][0] = __float_as_uint(As[st][m    ][kk+tig  ]);
                a[mt][1] = __float_as_uint(As[st][m + 8][kk+tig  ]);
                a[mt][2] = __float_as_uint(As[st][m    ][kk+tig+4]);
                a[mt][3] = __float_as_uint(As[st][m + 8][kk+tig+4]);
            }
            #pragma unroll
            for (int nt = 0; nt < 4; nt++) {
                int n = wn*32 + nt*8 + gid;
                bf[nt][0] = __float_as_uint(Bs[st][kk+tig  ][n]);
                bf[nt][1] = __float_as_uint(Bs[st][kk+tig+4][n]);
            }
            #pragma unroll
            for (int mt = 0; mt < 4; mt++)
                #pragma unroll
                for (int nt = 0; nt < 4; nt++)
                    mma_tf32(acc[mt][nt], a[mt], bf[nt]);
        }
        __syncthreads();
    }

    // fused epilogue
    const int nbase = n0 + wn*32;
    float2 gv[4];
    #pragma unroll
    for (int nt = 0; nt < 4; nt++)
        gv[nt] = *(const float2*)&g_q2c[b*H + nbase + nt*8 + 2*tig];
    #pragma unroll
    for (int mt = 0; mt < 4; mt++)
        #pragma unroll
        for (int r = 0; r < 2; r++) {
            int row = m0 + wm*64 + mt*16 + gid + 8*r;
            const float* crow = c + ((size_t)b*CLEN + row)*H;
            float* orow = out + ((size_t)b*CLEN + row)*(4*H);
            #pragma unroll
            for (int nt = 0; nt < 4; nt++) {
                int col = nbase + nt*8 + 2*tig;
                float2 cv = *(const float2*)&crow[col];
                float2 av = make_float2(acc[mt][nt][2*r], acc[mt][nt][2*r+1]);
                *(float2*)&orow[col]       = cv;
                *(float2*)&orow[H + col]   = av;
                *(float2*)&orow[2*H + col] = make_float2(cv.x*av.x, cv.y*av.y);
                *(float2*)&orow[3*H + col] = make_float2(cv.x*gv[nt].x, cv.y*gv[nt].y);
            }
        }
}

// ---------------------------------------------------------------------------
extern "C" void kernel_launch(void* const* d_in, const int* in_sizes, int n_in,
                              void* d_out, int out_size)
{
    const float* c    = (const float*)d_in[0];
    const float* q    = (const float*)d_in[1];
    const float* w_c  = (const float*)d_in[2];
    const float* b_c  = (const float*)d_in[3];
    const float* w_q  = (const float*)d_in[4];
    const float* b_q  = (const float*)d_in[5];
    const float* w_cq = (const float*)d_in[6];
    const float* b_cq = (const float*)d_in[7];
    float* out = (float*)d_out;

    {   // rounding prep
        size_t n4 = (size_t)B_*CLEN*(H/4) + (size_t)B_*QLEN*(H/4);
        prep_kernel<<<(unsigned)((n4 + 255)/256), 256>>>(
            (const float4*)c, (const float4*)q, (const float4*)w_cq);
    }
    {   // row dots
        int warps = B_*CLEN + B_*QLEN;
        uv_kernel<<<(warps*32 + 255)/256, 256>>>(c, q, w_c, b_c, w_q, b_q, b_cq);
    }
    {   // S
        dim3 grid(QLEN/128, CLEN/128, B_);
        gemm1_tc<<<grid, 256>>>();
    }
    {   // softmax rows
        int warps = B_*CLEN;
        softmax_kernel<<<(warps*32 + 255)/256, 256>>>();
    }
    bmz_kernel<<<B_, 256>>>();
    {
        dim3 grid(32, B_);
        q2c_part<<<grid, 256>>>(c);
    }
    q2c_reduce<<<B_, 256>>>();
    {   // c2q + fused output
        dim3 grid(H/128, CLEN/128, B_);
        gemm2_tc<<<grid, 256>>>(c, out);
    }
}